// round 1
// baseline (speedup 1.0000x reference)
#include <cuda_runtime.h>
#include <cstdint>
#include <cstddef>

// Problem constants
#define Bb 16
#define Ss 2048
#define Ee 1024

// ---------------- device scratch (static globals: allocation-free) ----------
__device__ float g_Q [(size_t)Bb * Ss * Ee];            // 134 MB
__device__ float g_K [(size_t)Bb * Ss * Ee];            // 134 MB
__device__ float g_Sc[(size_t)Bb * Ss * Ss];            // 268 MB
__device__ float g_l [Bb * Ss];                         // row logsumexp offsets
__device__ float g_w [Bb * Ss];                         // softmax column means
__device__ float g_u [Bb * Ee];                         // weighted x reduction

// ---------------------------------------------------------------------------
// NT SGEMM: C[m,n] = alpha * sum_k A[m,k]*B[n,k] (+ bias[n])
// A: M x K row-major, B: N x K row-major. M,N multiples of 128; K multiple of 8.
// blockIdx.z batches via sA/sB/sC element strides.
// 128x128 block tile, BK=8, 256 threads, 8x8 per-thread micro tile.
// ---------------------------------------------------------------------------
__global__ __launch_bounds__(256) void sgemm_nt(
    const float* __restrict__ A, const float* __restrict__ B,
    const float* __restrict__ bias, float* __restrict__ C,
    int M, int N, int K, float alpha,
    long long sA, long long sB, long long sC)
{
    __shared__ float As[8][128];
    __shared__ float Bs[8][128];

    const int tid  = threadIdx.x;
    const int trow = tid >> 4;        // 0..15  (micro-tile row group)
    const int tcol = tid & 15;        // 0..15  (micro-tile col group)
    const int lrow = tid >> 1;        // 0..127 (load row)
    const int lcol = (tid & 1) << 2;  // 0 or 4 (load col, float4)

    const float* Ab = A + (size_t)blockIdx.z * sA
                        + (size_t)(blockIdx.y * 128 + lrow) * K + lcol;
    const float* Bp = B + (size_t)blockIdx.z * sB
                        + (size_t)(blockIdx.x * 128 + lrow) * K + lcol;

    float acc[8][8];
#pragma unroll
    for (int i = 0; i < 8; i++)
#pragma unroll
        for (int j = 0; j < 8; j++) acc[i][j] = 0.0f;

    for (int k0 = 0; k0 < K; k0 += 8) {
        const float4 a4 = *(const float4*)(Ab + k0);
        const float4 b4 = *(const float4*)(Bp + k0);
        __syncthreads();  // previous tile's compute done before smem overwrite
        As[lcol + 0][lrow] = a4.x; As[lcol + 1][lrow] = a4.y;
        As[lcol + 2][lrow] = a4.z; As[lcol + 3][lrow] = a4.w;
        Bs[lcol + 0][lrow] = b4.x; Bs[lcol + 1][lrow] = b4.y;
        Bs[lcol + 2][lrow] = b4.z; Bs[lcol + 3][lrow] = b4.w;
        __syncthreads();

#pragma unroll
        for (int kk = 0; kk < 8; kk++) {
            float ra[8], rb[8];
#pragma unroll
            for (int i = 0; i < 8; i++) ra[i] = As[kk][trow * 8 + i];
#pragma unroll
            for (int j = 0; j < 8; j++) rb[j] = Bs[kk][tcol * 8 + j];
#pragma unroll
            for (int i = 0; i < 8; i++)
#pragma unroll
                for (int j = 0; j < 8; j++)
                    acc[i][j] += ra[i] * rb[j];
        }
    }

    const size_t cbase = (size_t)blockIdx.z * sC;
#pragma unroll
    for (int i = 0; i < 8; i++) {
        const int row = blockIdx.y * 128 + trow * 8 + i;
#pragma unroll
        for (int j = 0; j < 8; j++) {
            const int col = blockIdx.x * 128 + tcol * 8 + j;
            float v = alpha * acc[i][j];
            if (bias) v += __ldg(&bias[col]);
            C[cbase + (size_t)row * N + col] = v;
        }
    }
}

// ---------------------------------------------------------------------------
// Per-row softmax stats: l[r] = max(row) + log(sum exp(row - max))
// One block per (b,q) row of the score matrix.
// ---------------------------------------------------------------------------
__global__ __launch_bounds__(256) void row_stats(const float* __restrict__ Sc,
                                                 float* __restrict__ l)
{
    __shared__ float red[256];
    const size_t r = blockIdx.x;
    const float* row = Sc + r * (size_t)Ss;
    const int tid = threadIdx.x;

    float m = -3.0e38f;
    for (int i = tid; i < Ss; i += 256) m = fmaxf(m, row[i]);
    red[tid] = m; __syncthreads();
    for (int s = 128; s > 0; s >>= 1) {
        if (tid < s) red[tid] = fmaxf(red[tid], red[tid + s]);
        __syncthreads();
    }
    m = red[0];
    __syncthreads();

    float sum = 0.0f;
    for (int i = tid; i < Ss; i += 256) sum += __expf(row[i] - m);
    red[tid] = sum; __syncthreads();
    for (int s = 128; s > 0; s >>= 1) {
        if (tid < s) red[tid] += red[tid + s];
        __syncthreads();
    }
    if (tid == 0) l[r] = m + __logf(red[0]);
}

// ---------------------------------------------------------------------------
// Zero the atomic accumulators (w, u) — must run every launch.
// ---------------------------------------------------------------------------
__global__ void zero_wu(float* __restrict__ w, float* __restrict__ u)
{
    const int i = blockIdx.x * 256 + threadIdx.x;
    if (i < Bb * Ss) w[i] = 0.0f;
    if (i < Bb * Ee) u[i] = 0.0f;
}

// ---------------------------------------------------------------------------
// Softmax column means: w[b,k] = (1/S) * sum_q exp(Sc[b,q,k] - l[b,q])
// grid: (Ss/256, Bb, QCH) — q split into QCH chunks for parallelism; atomics.
// ---------------------------------------------------------------------------
#define QCH 8
__global__ __launch_bounds__(256) void col_mean(const float* __restrict__ Sc,
                                                const float* __restrict__ l,
                                                float* __restrict__ w)
{
    const int b  = blockIdx.y;
    const int k  = blockIdx.x * 256 + threadIdx.x;
    const int q0 = blockIdx.z * (Ss / QCH);
    const float* base = Sc + (size_t)b * Ss * Ss + k;
    const float* lb   = l + b * Ss;

    float acc = 0.0f;
#pragma unroll 4
    for (int q = q0; q < q0 + Ss / QCH; q++)
        acc += __expf(base[(size_t)q * Ss] - __ldg(&lb[q]));

    atomicAdd(&w[b * Ss + k], acc * (1.0f / Ss));
}

// ---------------------------------------------------------------------------
// u[b,f] = sum_k w[b,k] * x[b,k,f]    grid: (Ee/256, Bb, KCH) with atomics.
// ---------------------------------------------------------------------------
#define KCH 8
__global__ __launch_bounds__(256) void weighted_x(const float* __restrict__ x,
                                                  const float* __restrict__ w,
                                                  float* __restrict__ u)
{
    const int b  = blockIdx.y;
    const int f  = blockIdx.x * 256 + threadIdx.x;
    const int k0 = blockIdx.z * (Ss / KCH);
    const float* xb = x + (size_t)b * Ss * Ee + (size_t)k0 * Ee + f;
    const float* wb = w + b * Ss + k0;

    float acc = 0.0f;
#pragma unroll 4
    for (int k = 0; k < Ss / KCH; k++)
        acc += __ldg(&wb[k]) * xb[(size_t)k * Ee];

    atomicAdd(&u[b * Ee + f], acc);
}

// ---------------------------------------------------------------------------
// out[b,e] = sum_f u[b,f] * wv[e,f] + bv[e]
// block: 8 warps, each warp computes one output element by shfl-reduced dot.
// grid: (Ee/8, Bb)
// ---------------------------------------------------------------------------
__global__ __launch_bounds__(256) void out_gemm(const float* __restrict__ u,
                                                const float* __restrict__ wv,
                                                const float* __restrict__ bv,
                                                float* __restrict__ out)
{
    const int warp = threadIdx.x >> 5;
    const int lane = threadIdx.x & 31;
    const int e = blockIdx.x * 8 + warp;
    const int b = blockIdx.y;

    const float* ub = u + b * Ee;
    const float* wr = wv + (size_t)e * Ee;

    float acc = 0.0f;
    for (int f = lane; f < Ee; f += 32) acc += ub[f] * wr[f];
#pragma unroll
    for (int o = 16; o > 0; o >>= 1) acc += __shfl_down_sync(0xFFFFFFFFu, acc, o);

    if (lane == 0) out[b * Ee + e] = acc + __ldg(&bv[e]);
}

// ---------------------------------------------------------------------------
extern "C" void kernel_launch(void* const* d_in, const int* in_sizes, int n_in,
                              void* d_out, int out_size)
{
    const float* x  = (const float*)d_in[0];
    const float* wq = (const float*)d_in[1];
    const float* bq = (const float*)d_in[2];
    const float* wk = (const float*)d_in[3];
    const float* bk = (const float*)d_in[4];
    const float* wv = (const float*)d_in[5];
    const float* bv = (const float*)d_in[6];
    float* out = (float*)d_out;

    float *Q, *K, *Sc, *l, *w, *u;
    cudaGetSymbolAddress((void**)&Q,  g_Q);
    cudaGetSymbolAddress((void**)&K,  g_K);
    cudaGetSymbolAddress((void**)&Sc, g_Sc);
    cudaGetSymbolAddress((void**)&l,  g_l);
    cudaGetSymbolAddress((void**)&w,  g_w);
    cudaGetSymbolAddress((void**)&u,  g_u);

    const float inv_sqrt_e = 1.0f / 32.0f;  // 1/sqrt(1024)

    // 1-2) Q = x @ wq^T + bq ; K = x @ wk^T + bk     (M=B*S, N=E, K=E)
    {
        dim3 grid(Ee / 128, (Bb * Ss) / 128, 1);
        sgemm_nt<<<grid, 256>>>(x, wq, bq, Q, Bb * Ss, Ee, Ee, 1.0f, 0, 0, 0);
        sgemm_nt<<<grid, 256>>>(x, wk, bk, K, Bb * Ss, Ee, Ee, 1.0f, 0, 0, 0);
    }

    // 3) Sc[b] = (Q[b] @ K[b]^T) / sqrt(E)           (M=S, N=S, K=E, batched)
    {
        dim3 grid(Ss / 128, Ss / 128, Bb);
        sgemm_nt<<<grid, 256>>>(Q, K, nullptr, Sc, Ss, Ss, Ee, inv_sqrt_e,
                                (long long)Ss * Ee, (long long)Ss * Ee,
                                (long long)Ss * Ss);
    }

    // 4) per-row logsumexp offsets
    row_stats<<<Bb * Ss, 256>>>(Sc, l);

    // 5) zero atomic accumulators
    zero_wu<<<(Bb * Ss + 255) / 256, 256>>>(w, u);

    // 6) softmax column means
    {
        dim3 grid(Ss / 256, Bb, QCH);
        col_mean<<<grid, 256>>>(Sc, l, w);
    }

    // 7) u[b,:] = w[b,:] @ x[b]
    {
        dim3 grid(Ee / 256, Bb, KCH);
        weighted_x<<<grid, 256>>>(x, w, u);
    }

    // 8) out = u @ wv^T + bv
    {
        dim3 grid(Ee / 8, Bb);
        out_gemm<<<grid, 256>>>(u, wv, bv, out);
    }
}

// round 3
// speedup vs baseline: 3.0766x; 3.0766x over previous
#include <cuda_runtime.h>
#include <cuda_bf16.h>
#include <cstdint>
#include <cstddef>

// Problem constants
#define Bb 16
#define Ss 2048
#define Ee 1024

// ---------------- device scratch (static globals: allocation-free) ----------
__device__ __nv_bfloat16 g_xhi[(size_t)Bb * Ss * Ee];   // 67 MB
__device__ __nv_bfloat16 g_xlo[(size_t)Bb * Ss * Ee];   // 67 MB
__device__ __nv_bfloat16 g_Yhi[(size_t)Bb * Ss * Ee];   // 67 MB
__device__ __nv_bfloat16 g_Ylo[(size_t)Bb * Ss * Ee];   // 67 MB
__device__ float g_Mt  [(size_t)Ee * Ee];               // 4 MB  (M[e,f] transposed)
__device__ __nv_bfloat16 g_Mthi[(size_t)Ee * Ee];
__device__ __nv_bfloat16 g_Mtlo[(size_t)Ee * Ee];
__device__ float g_sv [Ee];                             // s = Wk^T bq
__device__ float g_t3s[Bb * Ss];                        // (x . s)/32
__device__ float g_Sc [(size_t)Bb * Ss * Ss];           // 268 MB scores
__device__ float g_l  [Bb * Ss];                        // row logsumexp
__device__ float g_w  [Bb * Ss];                        // softmax col means
__device__ float g_u  [Bb * Ee];                        // weighted x

// =========================== PTX helpers (base compute_103 only) ============
__device__ __forceinline__ uint32_t smem_u32(const void* p) {
    uint32_t a;
    asm("{ .reg .u64 t; cvta.to.shared.u64 t, %1; cvt.u32.u64 %0, t; }"
        : "=r"(a) : "l"(p));
    return a;
}
#define CP_ASYNC16(d, s) \
    asm volatile("cp.async.cg.shared.global [%0], [%1], 16;" :: "r"(d), "l"(s))
#define CP_COMMIT() asm volatile("cp.async.commit_group;" ::: "memory")
#define CP_WAIT(n)  asm volatile("cp.async.wait_group %0;" :: "n"(n) : "memory")

// SW64 swizzle for 64-byte rows: XOR col bits [5:4] with row bits [8:7]>>3
#define SWZ64(o) ((o) ^ (((o) >> 3) & 0x30))

__device__ __forceinline__ void ldsm_x4(uint32_t* r, uint32_t addr) {
    asm volatile("ldmatrix.sync.aligned.m8n8.x4.shared.b16 {%0,%1,%2,%3}, [%4];"
                 : "=r"(r[0]), "=r"(r[1]), "=r"(r[2]), "=r"(r[3])
                 : "r"(addr));
}
__device__ __forceinline__ void mma16816(float* c, const uint32_t* a,
                                         const uint32_t* b) {
    asm volatile(
        "mma.sync.aligned.m16n8k16.row.col.f32.bf16.bf16.f32 "
        "{%0,%1,%2,%3}, {%4,%5,%6,%7}, {%8,%9}, {%0,%1,%2,%3};"
        : "+f"(c[0]), "+f"(c[1]), "+f"(c[2]), "+f"(c[3])
        : "r"(a[0]), "r"(a[1]), "r"(a[2]), "r"(a[3]), "r"(b[0]), "r"(b[1]));
}

// ======================= bf16x3 NT GEMM via mma.sync ========================
// C[m,n] = alpha * sum_k A[m,k]*B[n,k]  (+ addv[n])
//   ~= Ahi.Bhi + Ahi.Blo + Alo.Bhi  (3 bf16 products, fp32 accum)
// A: M x K, B: N x K, both row-major bf16 hi/lo. M,N mult of 128, K mult of 32.
// out_mode 0: Cf fp32 (+addv[col]).  out_mode 1: Chi/Clo bf16 split.
#define NS 3
#define STAGE 32768              // 4 tiles x (128 x 32 bf16 = 8 KB)
#define GEMM_DSMEM (NS * STAGE + 1024)

__global__ __launch_bounds__(256) void gemm_bf16x3(
    const __nv_bfloat16* __restrict__ Ahi, const __nv_bfloat16* __restrict__ Alo,
    const __nv_bfloat16* __restrict__ Bhi, const __nv_bfloat16* __restrict__ Blo,
    float* __restrict__ Cf,
    __nv_bfloat16* __restrict__ Chi, __nv_bfloat16* __restrict__ Clo,
    const float* __restrict__ addv,
    int M, int N, int K, float alpha,
    long long sA, long long sB, long long sC, long long sAdd, int out_mode)
{
    extern __shared__ char dynsm[];
    const uint32_t sbase = (smem_u32(dynsm) + 1023u) & ~1023u;

    const int tid  = threadIdx.x;
    const int lane = tid & 31;
    const int wid  = tid >> 5;
    const int wm   = wid >> 2;       // 0..1 -> 64-row band
    const int wn   = wid & 3;        // 0..3 -> 32-col band
    const int NC   = K / 32;

    const size_t arow0 = (size_t)blockIdx.z * sA + (size_t)(blockIdx.y * 128) * K;
    const size_t brow0 = (size_t)blockIdx.z * sB + (size_t)(blockIdx.x * 128) * K;

    auto load_stage = [&](int c) {
        const uint32_t st = sbase + (uint32_t)(c % NS) * STAGE;
        const __nv_bfloat16* srcs[4] = {Ahi, Alo, Bhi, Blo};
        const size_t base[4] = {arow0, arow0, brow0, brow0};
        const int kc0 = c * 32;
#pragma unroll
        for (int t = 0; t < 4; t++) {
            const uint32_t tb = st + (uint32_t)t * 8192;
#pragma unroll
            for (int i = 0; i < 2; i++) {
                const int idx = tid + 256 * i;      // 0..511
                const int row = idx >> 2;
                const int ch  = idx & 3;
                const __nv_bfloat16* g =
                    srcs[t] + base[t] + (size_t)row * K + kc0 + ch * 8;
                CP_ASYNC16(tb + SWZ64((uint32_t)(row * 64 + ch * 16)), g);
            }
        }
        CP_COMMIT();
    };

    float acc[4][4][4];
#pragma unroll
    for (int i = 0; i < 4; i++)
#pragma unroll
        for (int j = 0; j < 4; j++)
#pragma unroll
            for (int r = 0; r < 4; r++) acc[i][j][r] = 0.0f;

    load_stage(0);
    load_stage(1);

    // per-lane ldmatrix address components
    const int a_r = wm * 64 + (lane & 7) + ((lane >> 3) & 1) * 8;  // + mi*16
    const int a_c = (lane >> 4) & 1;                               // + ks*2
    const int b_r = wn * 32 + (lane & 7) + ((lane >> 4) & 1) * 8;  // + p*16
    const int b_c = (lane >> 3) & 1;                               // + ks*2

    for (int c = 0; c < NC; c++) {
        CP_WAIT(1);
        __syncthreads();
        if (c + 2 < NC) load_stage(c + 2); else CP_COMMIT();

        const uint32_t st = sbase + (uint32_t)(c % NS) * STAGE;
#pragma unroll
        for (int ks = 0; ks < 2; ks++) {
            uint32_t ah[4][4], al[4][4], bh[4][2], bl[4][2];
#pragma unroll
            for (int mi = 0; mi < 4; mi++) {
                const uint32_t off =
                    SWZ64((uint32_t)((a_r + mi * 16) * 64 + (a_c + ks * 2) * 16));
                ldsm_x4(ah[mi], st + off);
                ldsm_x4(al[mi], st + 8192 + off);
            }
#pragma unroll
            for (int p = 0; p < 2; p++) {
                const uint32_t off =
                    SWZ64((uint32_t)((b_r + p * 16) * 64 + (b_c + ks * 2) * 16));
                uint32_t t0[4], t1[4];
                ldsm_x4(t0, st + 16384 + off);
                ldsm_x4(t1, st + 24576 + off);
                bh[2 * p][0] = t0[0]; bh[2 * p][1] = t0[1];
                bh[2 * p + 1][0] = t0[2]; bh[2 * p + 1][1] = t0[3];
                bl[2 * p][0] = t1[0]; bl[2 * p][1] = t1[1];
                bl[2 * p + 1][0] = t1[2]; bl[2 * p + 1][1] = t1[3];
            }
#pragma unroll
            for (int mi = 0; mi < 4; mi++)
#pragma unroll
                for (int ni = 0; ni < 4; ni++) {
                    mma16816(acc[mi][ni], ah[mi], bh[ni]);
                    mma16816(acc[mi][ni], ah[mi], bl[ni]);
                    mma16816(acc[mi][ni], al[mi], bh[ni]);
                }
        }
    }

    // ------------------------------ epilogue --------------------------------
    const int gr0 = blockIdx.y * 128 + wm * 64 + (lane >> 2);
    const int gc0 = blockIdx.x * 128 + wn * 32 + 2 * (lane & 3);
    const size_t cb = (size_t)blockIdx.z * sC;

#pragma unroll
    for (int mi = 0; mi < 4; mi++) {
#pragma unroll
        for (int ni = 0; ni < 4; ni++) {
            const int row = gr0 + mi * 16;
            const int col = gc0 + ni * 8;
            float v0 = acc[mi][ni][0] * alpha;
            float v1 = acc[mi][ni][1] * alpha;
            float v2 = acc[mi][ni][2] * alpha;
            float v3 = acc[mi][ni][3] * alpha;
            if (out_mode == 0) {
                if (addv) {
                    const float a0 = __ldg(&addv[(size_t)blockIdx.z * sAdd + col]);
                    const float a1 = __ldg(&addv[(size_t)blockIdx.z * sAdd + col + 1]);
                    v0 += a0; v1 += a1; v2 += a0; v3 += a1;
                }
                *(float2*)&Cf[cb + (size_t)row * N + col]       = make_float2(v0, v1);
                *(float2*)&Cf[cb + (size_t)(row + 8) * N + col] = make_float2(v2, v3);
            } else {
                const __nv_bfloat16 h0 = __float2bfloat16(v0);
                const __nv_bfloat16 h1 = __float2bfloat16(v1);
                const __nv_bfloat16 h2 = __float2bfloat16(v2);
                const __nv_bfloat16 h3 = __float2bfloat16(v3);
                const __nv_bfloat16 l0 = __float2bfloat16(v0 - __bfloat162float(h0));
                const __nv_bfloat16 l1 = __float2bfloat16(v1 - __bfloat162float(h1));
                const __nv_bfloat16 l2 = __float2bfloat16(v2 - __bfloat162float(h2));
                const __nv_bfloat16 l3 = __float2bfloat16(v3 - __bfloat162float(h3));
                *(__nv_bfloat162*)&Chi[cb + (size_t)row * N + col] =
                    __nv_bfloat162(h0, h1);
                *(__nv_bfloat162*)&Chi[cb + (size_t)(row + 8) * N + col] =
                    __nv_bfloat162(h2, h3);
                *(__nv_bfloat162*)&Clo[cb + (size_t)row * N + col] =
                    __nv_bfloat162(l0, l1);
                *(__nv_bfloat162*)&Clo[cb + (size_t)(row + 8) * N + col] =
                    __nv_bfloat162(l2, l3);
            }
        }
    }
}

// ============= TN fp32 sgemm (tiny): Mt[m,n] = sum_g A[g,m]*B[g,n] ==========
__global__ __launch_bounds__(256) void sgemm_tn(
    const float* __restrict__ A, const float* __restrict__ B,
    float* __restrict__ C, int M, int N, int K)
{
    __shared__ float As[8][128];
    __shared__ float Bs[8][128];
    const int tid  = threadIdx.x;
    const int trow = tid >> 4, tcol = tid & 15;
    const int krow = tid >> 5, col4 = (tid & 31) * 4;
    const int m0 = blockIdx.y * 128, n0 = blockIdx.x * 128;

    float acc[8][8];
#pragma unroll
    for (int i = 0; i < 8; i++)
#pragma unroll
        for (int j = 0; j < 8; j++) acc[i][j] = 0.0f;

    for (int k0 = 0; k0 < K; k0 += 8) {
        const float4 a4 = *(const float4*)&A[(size_t)(k0 + krow) * M + m0 + col4];
        const float4 b4 = *(const float4*)&B[(size_t)(k0 + krow) * N + n0 + col4];
        __syncthreads();
        *(float4*)&As[krow][col4] = a4;
        *(float4*)&Bs[krow][col4] = b4;
        __syncthreads();
#pragma unroll
        for (int kk = 0; kk < 8; kk++) {
            float ra[8], rb[8];
#pragma unroll
            for (int i = 0; i < 8; i++) ra[i] = As[kk][trow * 8 + i];
#pragma unroll
            for (int j = 0; j < 8; j++) rb[j] = Bs[kk][tcol * 8 + j];
#pragma unroll
            for (int i = 0; i < 8; i++)
#pragma unroll
                for (int j = 0; j < 8; j++) acc[i][j] += ra[i] * rb[j];
        }
    }
#pragma unroll
    for (int i = 0; i < 8; i++)
#pragma unroll
        for (int j = 0; j < 8; j++)
            C[(size_t)(m0 + trow * 8 + i) * N + n0 + tcol * 8 + j] = acc[i][j];
}

// ===================== fp32 -> bf16 hi/lo split =============================
__global__ __launch_bounds__(256) void split_f32(
    const float* __restrict__ in, __nv_bfloat16* __restrict__ hi,
    __nv_bfloat16* __restrict__ lo, int n4)
{
    const int idx = blockIdx.x * 256 + threadIdx.x;
    if (idx >= n4) return;
    const float4 v = ((const float4*)in)[idx];
    float vv[4] = {v.x, v.y, v.z, v.w};
    __nv_bfloat16 h[4], l[4];
#pragma unroll
    for (int j = 0; j < 4; j++) {
        h[j] = __float2bfloat16(vv[j]);
        l[j] = __float2bfloat16(vv[j] - __bfloat162float(h[j]));
    }
    ((__nv_bfloat162*)hi)[idx * 2 + 0] = __nv_bfloat162(h[0], h[1]);
    ((__nv_bfloat162*)hi)[idx * 2 + 1] = __nv_bfloat162(h[2], h[3]);
    ((__nv_bfloat162*)lo)[idx * 2 + 0] = __nv_bfloat162(l[0], l[1]);
    ((__nv_bfloat162*)lo)[idx * 2 + 1] = __nv_bfloat162(l[2], l[3]);
}

// s[f] = sum_e Wk[e,f] * bq[e]
__global__ __launch_bounds__(256) void calc_s(
    const float* __restrict__ Wk, const float* __restrict__ bq,
    float* __restrict__ s)
{
    const int f = blockIdx.x * 256 + threadIdx.x;
    float acc = 0.0f;
    for (int e = 0; e < Ee; e++) acc += Wk[(size_t)e * Ee + f] * __ldg(&bq[e]);
    s[f] = acc;
}

// t3s[r] = (x[r,:] . s) / 32   (warp per row)
__global__ __launch_bounds__(256) void t3_kernel(
    const float* __restrict__ x, const float* __restrict__ s,
    float* __restrict__ t3s)
{
    const int warp = threadIdx.x >> 5, lane = threadIdx.x & 31;
    const int row = blockIdx.x * 8 + warp;
    const float* xr = x + (size_t)row * Ee;
    float acc = 0.0f;
    for (int e = lane; e < Ee; e += 32) acc += xr[e] * __ldg(&s[e]);
#pragma unroll
    for (int o = 16; o > 0; o >>= 1) acc += __shfl_down_sync(0xFFFFFFFFu, acc, o);
    if (lane == 0) t3s[row] = acc * (1.0f / 32.0f);
}

// ============ per-row online logsumexp: l[r] = m + log(sum exp) =============
__global__ __launch_bounds__(256) void row_stats(const float* __restrict__ Sc,
                                                 float* __restrict__ l)
{
    __shared__ float sm[256], ss[256];
    const size_t r = blockIdx.x;
    const float4* row = (const float4*)(Sc + r * (size_t)Ss);
    const int tid = threadIdx.x;

    float m = -3.0e38f, s = 0.0f;
    for (int i = tid; i < Ss / 4; i += 256) {
        const float4 v = row[i];
        const float vv[4] = {v.x, v.y, v.z, v.w};
#pragma unroll
        for (int j = 0; j < 4; j++) {
            const float nm = fmaxf(m, vv[j]);
            s = s * __expf(m - nm) + __expf(vv[j] - nm);
            m = nm;
        }
    }
    sm[tid] = m; ss[tid] = s;
    __syncthreads();
    for (int st = 128; st > 0; st >>= 1) {
        if (tid < st) {
            const float m2 = sm[tid + st], s2 = ss[tid + st];
            const float nm = fmaxf(sm[tid], m2);
            ss[tid] = ss[tid] * __expf(sm[tid] - nm) + s2 * __expf(m2 - nm);
            sm[tid] = nm;
        }
        __syncthreads();
    }
    if (tid == 0) l[r] = sm[0] + __logf(ss[0]);
}

__global__ void zero_wu(float* __restrict__ w, float* __restrict__ u)
{
    const int i = blockIdx.x * 256 + threadIdx.x;
    if (i < Bb * Ss) w[i] = 0.0f;
    if (i < Bb * Ee) u[i] = 0.0f;
}

#define QCH 8
__global__ __launch_bounds__(256) void col_mean(const float* __restrict__ Sc,
                                                const float* __restrict__ l,
                                                float* __restrict__ w)
{
    const int b  = blockIdx.y;
    const int k  = blockIdx.x * 256 + threadIdx.x;
    const int q0 = blockIdx.z * (Ss / QCH);
    const float* base = Sc + (size_t)b * Ss * Ss + k;
    const float* lb   = l + b * Ss;
    float acc = 0.0f;
#pragma unroll 4
    for (int q = q0; q < q0 + Ss / QCH; q++)
        acc += __expf(base[(size_t)q * Ss] - __ldg(&lb[q]));
    atomicAdd(&w[b * Ss + k], acc * (1.0f / Ss));
}

#define KCH 8
__global__ __launch_bounds__(256) void weighted_x(const float* __restrict__ x,
                                                  const float* __restrict__ w,
                                                  float* __restrict__ u)
{
    const int b  = blockIdx.y;
    const int f  = blockIdx.x * 256 + threadIdx.x;
    const int k0 = blockIdx.z * (Ss / KCH);
    const float* xb = x + (size_t)b * Ss * Ee + (size_t)k0 * Ee + f;
    const float* wb = w + b * Ss + k0;
    float acc = 0.0f;
#pragma unroll 4
    for (int k = 0; k < Ss / KCH; k++)
        acc += __ldg(&wb[k]) * xb[(size_t)k * Ee];
    atomicAdd(&u[b * Ee + f], acc);
}

__global__ __launch_bounds__(256) void out_gemm(const float* __restrict__ u,
                                                const float* __restrict__ wv,
                                                const float* __restrict__ bv,
                                                float* __restrict__ out)
{
    const int warp = threadIdx.x >> 5, lane = threadIdx.x & 31;
    const int e = blockIdx.x * 8 + warp;
    const int b = blockIdx.y;
    const float* ub = u + b * Ee;
    const float* wr = wv + (size_t)e * Ee;
    float acc = 0.0f;
    for (int f = lane; f < Ee; f += 32) acc += ub[f] * wr[f];
#pragma unroll
    for (int o = 16; o > 0; o >>= 1) acc += __shfl_down_sync(0xFFFFFFFFu, acc, o);
    if (lane == 0) out[b * Ee + e] = acc + __ldg(&bv[e]);
}

// ---------------------------------------------------------------------------
extern "C" void kernel_launch(void* const* d_in, const int* in_sizes, int n_in,
                              void* d_out, int out_size)
{
    const float* x  = (const float*)d_in[0];
    const float* wq = (const float*)d_in[1];
    const float* bq = (const float*)d_in[2];
    const float* wk = (const float*)d_in[3];
    const float* bk = (const float*)d_in[4];
    const float* wv = (const float*)d_in[5];
    const float* bv = (const float*)d_in[6];
    float* out = (float*)d_out;
    (void)bk;  // cancels in softmax (constant along k)

    __nv_bfloat16 *xhi, *xlo, *Yhi, *Ylo, *Mthi, *Mtlo;
    float *Mt, *sv, *t3s, *Sc, *l, *w, *u;
    cudaGetSymbolAddress((void**)&xhi,  g_xhi);
    cudaGetSymbolAddress((void**)&xlo,  g_xlo);
    cudaGetSymbolAddress((void**)&Yhi,  g_Yhi);
    cudaGetSymbolAddress((void**)&Ylo,  g_Ylo);
    cudaGetSymbolAddress((void**)&Mt,   g_Mt);
    cudaGetSymbolAddress((void**)&Mthi, g_Mthi);
    cudaGetSymbolAddress((void**)&Mtlo, g_Mtlo);
    cudaGetSymbolAddress((void**)&sv,   g_sv);
    cudaGetSymbolAddress((void**)&t3s,  g_t3s);
    cudaGetSymbolAddress((void**)&Sc,   g_Sc);
    cudaGetSymbolAddress((void**)&l,    g_l);
    cudaGetSymbolAddress((void**)&w,    g_w);
    cudaGetSymbolAddress((void**)&u,    g_u);

    cudaFuncSetAttribute(gemm_bf16x3,
                         cudaFuncAttributeMaxDynamicSharedMemorySize, GEMM_DSMEM);

    const long long SE  = (long long)Ss * Ee;
    const long long SS2 = (long long)Ss * Ss;

    // 1) split x into bf16 hi/lo
    split_f32<<<(Bb * Ss * Ee / 4) / 256, 256>>>(x, xhi, xlo, Bb * Ss * Ee / 4);

    // 2) Mt[f,e] = sum_g Wk[g,f] Wq[g,e]  (= (Wq^T Wk)[e,f]), then split
    {
        dim3 grid(Ee / 128, Ee / 128);
        sgemm_tn<<<grid, 256>>>(wk, wq, Mt, Ee, Ee, Ee);
    }
    split_f32<<<(Ee * Ee / 4) / 256, 256>>>(Mt, Mthi, Mtlo, Ee * Ee / 4);

    // 3) s = Wk^T bq ; t3s = (x . s)/32
    calc_s<<<Ee / 256, 256>>>(wk, bq, sv);
    t3_kernel<<<Bb * Ss / 8, 256>>>(x, sv, t3s);

    // 4) GEMM1: Y = x @ Mt^T  -> bf16 hi/lo   (M=B*S, N=E, K=E)
    {
        dim3 grid(Ee / 128, (Bb * Ss) / 128, 1);
        gemm_bf16x3<<<grid, 256, GEMM_DSMEM>>>(
            xhi, xlo, Mthi, Mtlo, nullptr, Yhi, Ylo, nullptr,
            Bb * Ss, Ee, Ee, 1.0f, 0, 0, 0, 0, 1);
    }

    // 5) GEMM2: Sc[b] = (Y[b] @ x[b]^T)/32 + t3s[b,:]   (M=S, N=S, K=E)
    {
        dim3 grid(Ss / 128, Ss / 128, Bb);
        gemm_bf16x3<<<grid, 256, GEMM_DSMEM>>>(
            Yhi, Ylo, xhi, xlo, Sc, nullptr, nullptr, t3s,
            Ss, Ss, Ee, 1.0f / 32.0f, SE, SE, SS2, Ss, 0);
    }

    // 6) softmax row stats, column means, weighted x, final projection
    row_stats<<<Bb * Ss, 256>>>(Sc, l);
    zero_wu<<<(Bb * Ss + 255) / 256, 256>>>(w, u);
    {
        dim3 grid(Ss / 256, Bb, QCH);
        col_mean<<<grid, 256>>>(Sc, l, w);
    }
    {
        dim3 grid(Ee / 256, Bb, KCH);
        weighted_x<<<grid, 256>>>(x, w, u);
    }
    {
        dim3 grid(Ee / 8, Bb);
        out_gemm<<<grid, 256>>>(u, wv, bv, out);
    }
}

// round 4
// speedup vs baseline: 8.1362x; 2.6446x over previous
#include <cuda_runtime.h>
#include <cuda_fp16.h>
#include <cstdint>
#include <cstddef>

// Problem constants
#define Bb 16
#define Ss 2048
#define Ee 1024

// ---------------- device scratch (static globals: allocation-free) ----------
__device__ __half g_xh [(size_t)Bb * Ss * Ee];          // 67 MB  x in fp16
__device__ __half g_Yh [(size_t)Bb * Ss * Ee];          // 67 MB  Y = x @ Mt^T
__device__ __half g_E  [(size_t)Bb * Ss * Ss];          // 134 MB exp(score-4)
__device__ float  g_Mt  [(size_t)Ee * Ee];              // 4 MB   Wk^T Wq (fp32)
__device__ __half g_Mth[(size_t)Ee * Ee];               // 2 MB
__device__ float  g_sv [Ee];                            // s = Wk^T bq
__device__ float  g_t3s[Bb * Ss];                       // (x . s)/32
__device__ float  g_r  [Bb * Ss];                       // row sums of E -> 1/r
__device__ float  g_w  [Bb * Ss];                       // softmax col means
__device__ float  g_u  [Bb * Ee];                       // weighted x

// =========================== PTX helpers (base compute_103) =================
__device__ __forceinline__ uint32_t smem_u32(const void* p) {
    uint32_t a;
    asm("{ .reg .u64 t; cvta.to.shared.u64 t, %1; cvt.u32.u64 %0, t; }"
        : "=r"(a) : "l"(p));
    return a;
}
#define CP_ASYNC16(d, s) \
    asm volatile("cp.async.cg.shared.global [%0], [%1], 16;" :: "r"(d), "l"(s))
#define CP_COMMIT() asm volatile("cp.async.commit_group;" ::: "memory")
#define CP_WAIT(n)  asm volatile("cp.async.wait_group %0;" :: "n"(n) : "memory")

// SW64 swizzle for 64-byte rows
#define SWZ64(o) ((o) ^ (((o) >> 3) & 0x30))

__device__ __forceinline__ void ldsm_x4(uint32_t* r, uint32_t addr) {
    asm volatile("ldmatrix.sync.aligned.m8n8.x4.shared.b16 {%0,%1,%2,%3}, [%4];"
                 : "=r"(r[0]), "=r"(r[1]), "=r"(r[2]), "=r"(r[3])
                 : "r"(addr));
}
__device__ __forceinline__ void mma16816(float* c, const uint32_t* a,
                                         const uint32_t* b) {
    asm volatile(
        "mma.sync.aligned.m16n8k16.row.col.f32.f16.f16.f32 "
        "{%0,%1,%2,%3}, {%4,%5,%6,%7}, {%8,%9}, {%0,%1,%2,%3};"
        : "+f"(c[0]), "+f"(c[1]), "+f"(c[2]), "+f"(c[3])
        : "r"(a[0]), "r"(a[1]), "r"(a[2]), "r"(a[3]), "r"(b[0]), "r"(b[1]));
}

// ======================= fp16 NT GEMM via mma.sync ==========================
// out_mode 1: Ch[m,n] = fp16( alpha * sum_k A[m,k]*B[n,k] )
// out_mode 2: v = alpha*acc + addv[col];  E = fp16(exp(v-4));
//             row sums of exp atomically added to rsum[b*Ss + row].
// A: M x K fp16 row-major, B: N x K fp16 row-major. 128x128x32 tiles, 8 warps.
#define NS 3
#define STAGE 16384              // A 8 KB + B 8 KB
#define GEMM_DSMEM (NS * STAGE + 1024)

__global__ __launch_bounds__(256) void gemm_f16(
    const __half* __restrict__ A, const __half* __restrict__ B,
    __half* __restrict__ C, const float* __restrict__ addv,
    float* __restrict__ rsum,
    int M, int N, int K, float alpha,
    long long sA, long long sB, long long sC, long long sAdd, int out_mode)
{
    extern __shared__ char dynsm[];
    const uint32_t sbase = (smem_u32(dynsm) + 1023u) & ~1023u;

    const int tid  = threadIdx.x;
    const int lane = tid & 31;
    const int wid  = tid >> 5;
    const int wm   = wid >> 2;       // 0..1 -> 64-row band
    const int wn   = wid & 3;        // 0..3 -> 32-col band
    const int NC   = K / 32;

    const size_t arow0 = (size_t)blockIdx.z * sA + (size_t)(blockIdx.y * 128) * K;
    const size_t brow0 = (size_t)blockIdx.z * sB + (size_t)(blockIdx.x * 128) * K;

    auto load_stage = [&](int c) {
        const uint32_t st = sbase + (uint32_t)(c % NS) * STAGE;
        const int kc0 = c * 32;
#pragma unroll
        for (int t = 0; t < 2; t++) {
            const __half* src = t ? B : A;
            const size_t  bs  = t ? brow0 : arow0;
            const uint32_t tb = st + (uint32_t)t * 8192;
#pragma unroll
            for (int i = 0; i < 2; i++) {
                const int idx = tid + 256 * i;      // 0..511
                const int row = idx >> 2;
                const int ch  = idx & 3;
                const __half* g = src + bs + (size_t)row * K + kc0 + ch * 8;
                CP_ASYNC16(tb + SWZ64((uint32_t)(row * 64 + ch * 16)), g);
            }
        }
        CP_COMMIT();
    };

    float acc[4][4][4];
#pragma unroll
    for (int i = 0; i < 4; i++)
#pragma unroll
        for (int j = 0; j < 4; j++)
#pragma unroll
            for (int r = 0; r < 4; r++) acc[i][j][r] = 0.0f;

    load_stage(0);
    load_stage(1);

    const int a_r = wm * 64 + (lane & 7) + ((lane >> 3) & 1) * 8;  // + mi*16
    const int a_c = (lane >> 4) & 1;                               // + ks*2
    const int b_r = wn * 32 + (lane & 7) + ((lane >> 4) & 1) * 8;  // + p*16
    const int b_c = (lane >> 3) & 1;                               // + ks*2

    for (int c = 0; c < NC; c++) {
        CP_WAIT(1);
        __syncthreads();
        if (c + 2 < NC) load_stage(c + 2); else CP_COMMIT();

        const uint32_t st = sbase + (uint32_t)(c % NS) * STAGE;
#pragma unroll
        for (int ks = 0; ks < 2; ks++) {
            uint32_t ah[4][4], bh[4][2];
#pragma unroll
            for (int mi = 0; mi < 4; mi++) {
                const uint32_t off =
                    SWZ64((uint32_t)((a_r + mi * 16) * 64 + (a_c + ks * 2) * 16));
                ldsm_x4(ah[mi], st + off);
            }
#pragma unroll
            for (int p = 0; p < 2; p++) {
                const uint32_t off =
                    SWZ64((uint32_t)((b_r + p * 16) * 64 + (b_c + ks * 2) * 16));
                uint32_t t0[4];
                ldsm_x4(t0, st + 8192 + off);
                bh[2 * p][0] = t0[0]; bh[2 * p][1] = t0[1];
                bh[2 * p + 1][0] = t0[2]; bh[2 * p + 1][1] = t0[3];
            }
#pragma unroll
            for (int mi = 0; mi < 4; mi++)
#pragma unroll
                for (int ni = 0; ni < 4; ni++)
                    mma16816(acc[mi][ni], ah[mi], bh[ni]);
        }
    }

    // ------------------------------ epilogue --------------------------------
    const int gr0 = blockIdx.y * 128 + wm * 64 + (lane >> 2);
    const int gc0 = blockIdx.x * 128 + wn * 32 + 2 * (lane & 3);
    const size_t cb = (size_t)blockIdx.z * sC;

    if (out_mode == 1) {
#pragma unroll
        for (int mi = 0; mi < 4; mi++)
#pragma unroll
            for (int ni = 0; ni < 4; ni++) {
                const int row = gr0 + mi * 16;
                const int col = gc0 + ni * 8;
                *(__half2*)&C[cb + (size_t)row * N + col] =
                    __floats2half2_rn(acc[mi][ni][0] * alpha,
                                      acc[mi][ni][1] * alpha);
                *(__half2*)&C[cb + (size_t)(row + 8) * N + col] =
                    __floats2half2_rn(acc[mi][ni][2] * alpha,
                                      acc[mi][ni][3] * alpha);
            }
    } else {
        const float* av = addv + (size_t)blockIdx.z * sAdd;
        float* rb = rsum + (size_t)blockIdx.z * Ss;
#pragma unroll
        for (int mi = 0; mi < 4; mi++) {
            float s_lo = 0.0f, s_hi = 0.0f;
            const int row = gr0 + mi * 16;
#pragma unroll
            for (int ni = 0; ni < 4; ni++) {
                const int col = gc0 + ni * 8;
                const float a0 = __ldg(&av[col]);
                const float a1 = __ldg(&av[col + 1]);
                const float e0 = __expf(acc[mi][ni][0] * alpha + a0 - 4.0f);
                const float e1 = __expf(acc[mi][ni][1] * alpha + a1 - 4.0f);
                const float e2 = __expf(acc[mi][ni][2] * alpha + a0 - 4.0f);
                const float e3 = __expf(acc[mi][ni][3] * alpha + a1 - 4.0f);
                s_lo += e0 + e1;
                s_hi += e2 + e3;
                *(__half2*)&C[cb + (size_t)row * N + col] =
                    __floats2half2_rn(e0, e1);
                *(__half2*)&C[cb + (size_t)(row + 8) * N + col] =
                    __floats2half2_rn(e2, e3);
            }
            s_lo += __shfl_xor_sync(0xFFFFFFFFu, s_lo, 1);
            s_lo += __shfl_xor_sync(0xFFFFFFFFu, s_lo, 2);
            s_hi += __shfl_xor_sync(0xFFFFFFFFu, s_hi, 1);
            s_hi += __shfl_xor_sync(0xFFFFFFFFu, s_hi, 2);
            if ((lane & 3) == 0) {
                atomicAdd(&rb[row], s_lo);
                atomicAdd(&rb[row + 8], s_hi);
            }
        }
    }
}

// ============= TN fp32 sgemm split-K: Mt[m,n] += sum_g A[g,m]*B[g,n] ========
#define MT_SPLITK 4
__global__ __launch_bounds__(256) void sgemm_tn_splitk(
    const float* __restrict__ A, const float* __restrict__ B,
    float* __restrict__ C, int M, int N, int K)
{
    __shared__ float As[8][128];
    __shared__ float Bs[8][128];
    const int tid  = threadIdx.x;
    const int trow = tid >> 4, tcol = tid & 15;
    const int krow = tid >> 5, col4 = (tid & 31) * 4;
    const int m0 = blockIdx.y * 128, n0 = blockIdx.x * 128;
    const int kslice = K / MT_SPLITK;
    const int kbeg = blockIdx.z * kslice, kend = kbeg + kslice;

    float acc[8][8];
#pragma unroll
    for (int i = 0; i < 8; i++)
#pragma unroll
        for (int j = 0; j < 8; j++) acc[i][j] = 0.0f;

    for (int k0 = kbeg; k0 < kend; k0 += 8) {
        const float4 a4 = *(const float4*)&A[(size_t)(k0 + krow) * M + m0 + col4];
        const float4 b4 = *(const float4*)&B[(size_t)(k0 + krow) * N + n0 + col4];
        __syncthreads();
        *(float4*)&As[krow][col4] = a4;
        *(float4*)&Bs[krow][col4] = b4;
        __syncthreads();
#pragma unroll
        for (int kk = 0; kk < 8; kk++) {
            float ra[8], rb[8];
#pragma unroll
            for (int i = 0; i < 8; i++) ra[i] = As[kk][trow * 8 + i];
#pragma unroll
            for (int j = 0; j < 8; j++) rb[j] = Bs[kk][tcol * 8 + j];
#pragma unroll
            for (int i = 0; i < 8; i++)
#pragma unroll
                for (int j = 0; j < 8; j++) acc[i][j] += ra[i] * rb[j];
        }
    }
#pragma unroll
    for (int i = 0; i < 8; i++)
#pragma unroll
        for (int j = 0; j < 8; j++)
            atomicAdd(&C[(size_t)(m0 + trow * 8 + i) * N + n0 + tcol * 8 + j],
                      acc[i][j]);
}

// ===================== conversions / zeroing ================================
__global__ __launch_bounds__(256) void cvt_f32_f16(
    const float* __restrict__ in, __half* __restrict__ out, int n4)
{
    const int idx = blockIdx.x * 256 + threadIdx.x;
    if (idx >= n4) return;
    const float4 v = ((const float4*)in)[idx];
    ((__half2*)out)[idx * 2 + 0] = __floats2half2_rn(v.x, v.y);
    ((__half2*)out)[idx * 2 + 1] = __floats2half2_rn(v.z, v.w);
}

__global__ void zero_f(float* __restrict__ p, int n)
{
    const int i = blockIdx.x * 256 + threadIdx.x;
    if (i < n) p[i] = 0.0f;
}

// s[f] += sum_{e in chunk} Wk[e,f]*bq[e]   grid (Ee/256, ECH)
#define ECH 16
__global__ __launch_bounds__(256) void calc_s(
    const float* __restrict__ Wk, const float* __restrict__ bq,
    float* __restrict__ s)
{
    const int f  = blockIdx.x * 256 + threadIdx.x;
    const int e0 = blockIdx.y * (Ee / ECH);
    float acc = 0.0f;
#pragma unroll 4
    for (int e = e0; e < e0 + Ee / ECH; e++)
        acc += Wk[(size_t)e * Ee + f] * __ldg(&bq[e]);
    atomicAdd(&s[f], acc);
}

// t3s[r] = (x[r,:] . s) / 32   (warp per row)
__global__ __launch_bounds__(256) void t3_kernel(
    const float* __restrict__ x, const float* __restrict__ s,
    float* __restrict__ t3s)
{
    const int warp = threadIdx.x >> 5, lane = threadIdx.x & 31;
    const int row = blockIdx.x * 8 + warp;
    const float* xr = x + (size_t)row * Ee;
    float acc = 0.0f;
    for (int e = lane; e < Ee; e += 32) acc += xr[e] * __ldg(&s[e]);
#pragma unroll
    for (int o = 16; o > 0; o >>= 1) acc += __shfl_down_sync(0xFFFFFFFFu, acc, o);
    if (lane == 0) t3s[row] = acc * (1.0f / 32.0f);
}

__global__ void inv_r(float* __restrict__ r, int n)
{
    const int i = blockIdx.x * 256 + threadIdx.x;
    if (i < n) r[i] = 1.0f / r[i];
}

// w[b,k] += (1/S) * sum_{q in chunk} E[b,q,k] * ri[b,q]
#define QCH 8
__global__ __launch_bounds__(256) void col_mean(const __half* __restrict__ E,
                                                const float* __restrict__ ri,
                                                float* __restrict__ w)
{
    const int b  = blockIdx.y;
    const int k  = blockIdx.x * 256 + threadIdx.x;
    const int q0 = blockIdx.z * (Ss / QCH);
    const __half* base = E + (size_t)b * Ss * Ss + k;
    const float* rb = ri + b * Ss;
    float acc = 0.0f;
#pragma unroll 4
    for (int q = q0; q < q0 + Ss / QCH; q++)
        acc += __half2float(base[(size_t)q * Ss]) * __ldg(&rb[q]);
    atomicAdd(&w[b * Ss + k], acc * (1.0f / Ss));
}

// u[b,f] += sum_{k in chunk} w[b,k] * x[b,k,f]
#define KCH 8
__global__ __launch_bounds__(256) void weighted_x(const float* __restrict__ x,
                                                  const float* __restrict__ w,
                                                  float* __restrict__ u)
{
    const int b  = blockIdx.y;
    const int f  = blockIdx.x * 256 + threadIdx.x;
    const int k0 = blockIdx.z * (Ss / KCH);
    const float* xb = x + (size_t)b * Ss * Ee + (size_t)k0 * Ee + f;
    const float* wb = w + b * Ss + k0;
    float acc = 0.0f;
#pragma unroll 4
    for (int k = 0; k < Ss / KCH; k++)
        acc += __ldg(&wb[k]) * xb[(size_t)k * Ee];
    atomicAdd(&u[b * Ee + f], acc);
}

__global__ __launch_bounds__(256) void out_gemm(const float* __restrict__ u,
                                                const float* __restrict__ wv,
                                                const float* __restrict__ bv,
                                                float* __restrict__ out)
{
    const int warp = threadIdx.x >> 5, lane = threadIdx.x & 31;
    const int e = blockIdx.x * 8 + warp;
    const int b = blockIdx.y;
    const float* ub = u + b * Ee;
    const float* wr = wv + (size_t)e * Ee;
    float acc = 0.0f;
    for (int f = lane; f < Ee; f += 32) acc += ub[f] * wr[f];
#pragma unroll
    for (int o = 16; o > 0; o >>= 1) acc += __shfl_down_sync(0xFFFFFFFFu, acc, o);
    if (lane == 0) out[b * Ee + e] = acc + __ldg(&bv[e]);
}

// ---------------------------------------------------------------------------
extern "C" void kernel_launch(void* const* d_in, const int* in_sizes, int n_in,
                              void* d_out, int out_size)
{
    const float* x  = (const float*)d_in[0];
    const float* wq = (const float*)d_in[1];
    const float* bq = (const float*)d_in[2];
    const float* wk = (const float*)d_in[3];
    const float* bk = (const float*)d_in[4];
    const float* wv = (const float*)d_in[5];
    const float* bv = (const float*)d_in[6];
    float* out = (float*)d_out;
    (void)bk;  // constant along k -> cancels in softmax

    __half *xh, *Yh, *E, *Mth;
    float *Mt, *sv, *t3s, *r, *w, *u;
    cudaGetSymbolAddress((void**)&xh,  g_xh);
    cudaGetSymbolAddress((void**)&Yh,  g_Yh);
    cudaGetSymbolAddress((void**)&E,   g_E);
    cudaGetSymbolAddress((void**)&Mt,  g_Mt);
    cudaGetSymbolAddress((void**)&Mth, g_Mth);
    cudaGetSymbolAddress((void**)&sv,  g_sv);
    cudaGetSymbolAddress((void**)&t3s, g_t3s);
    cudaGetSymbolAddress((void**)&r,   g_r);
    cudaGetSymbolAddress((void**)&w,   g_w);
    cudaGetSymbolAddress((void**)&u,   g_u);

    cudaFuncSetAttribute(gemm_f16,
                         cudaFuncAttributeMaxDynamicSharedMemorySize, GEMM_DSMEM);

    const long long SE  = (long long)Ss * Ee;
    const long long SS2 = (long long)Ss * Ss;

    // 0) zero accumulators (Mt, sv, r, w, u)
    zero_f<<<(Ee * Ee + 255) / 256, 256>>>(Mt, Ee * Ee);
    zero_f<<<(Ee + 255) / 256, 256>>>(sv, Ee);
    zero_f<<<(Bb * Ss + 255) / 256, 256>>>(r, Bb * Ss);
    zero_f<<<(Bb * Ss + 255) / 256, 256>>>(w, Bb * Ss);
    zero_f<<<(Bb * Ee + 255) / 256, 256>>>(u, Bb * Ee);

    // 1) x -> fp16
    cvt_f32_f16<<<(Bb * Ss * Ee / 4 + 255) / 256, 256>>>(x, xh, Bb * Ss * Ee / 4);

    // 2) Mt[f,e] = sum_g Wk[g,f] Wq[g,e]  (split-K, atomic), then -> fp16
    {
        dim3 grid(Ee / 128, Ee / 128, MT_SPLITK);
        sgemm_tn_splitk<<<grid, 256>>>(wk, wq, Mt, Ee, Ee, Ee);
    }
    cvt_f32_f16<<<(Ee * Ee / 4 + 255) / 256, 256>>>(Mt, Mth, Ee * Ee / 4);

    // 3) s = Wk^T bq ; t3s = (x . s)/32
    {
        dim3 grid(Ee / 256, ECH);
        calc_s<<<grid, 256>>>(wk, bq, sv);
    }
    t3_kernel<<<Bb * Ss / 8, 256>>>(x, sv, t3s);

    // 4) GEMM1: Yh = xh @ Mth^T   (M=B*S, N=E, K=E)
    {
        dim3 grid(Ee / 128, (Bb * Ss) / 128, 1);
        gemm_f16<<<grid, 256, GEMM_DSMEM>>>(
            xh, Mth, Yh, nullptr, nullptr,
            Bb * Ss, Ee, Ee, 1.0f, 0, 0, 0, 0, 1);
    }

    // 5) GEMM2 + fused softmax-numerator: E[b,q,k] = exp(score-4), r[b,q] = row sums
    {
        dim3 grid(Ss / 128, Ss / 128, Bb);
        gemm_f16<<<grid, 256, GEMM_DSMEM>>>(
            Yh, xh, E, t3s, r,
            Ss, Ss, Ee, 1.0f / 32.0f, SE, SE, SS2, Ss, 2);
    }

    // 6) r -> 1/r ; column means ; weighted x ; final projection
    inv_r<<<(Bb * Ss + 255) / 256, 256>>>(r, Bb * Ss);
    {
        dim3 grid(Ss / 256, Bb, QCH);
        col_mean<<<grid, 256>>>(E, r, w);
    }
    {
        dim3 grid(Ee / 256, Bb, KCH);
        weighted_x<<<grid, 256>>>(x, w, u);
    }
    {
        dim3 grid(Ee / 8, Bb);
        out_gemm<<<grid, 256>>>(u, wv, bv, out);
    }
}